// round 14
// baseline (speedup 1.0000x reference)
#include <cuda_runtime.h>
#include <cuda_fp16.h>
#include <cstdint>

// ---------------------------------------------------------------------------
// Poly2d via warp-level HMMA (mma.sync m16n8k16, fp16 in / fp32 acc).
// 54 features/channel; K packed 2x56=112 per channel pair (7 k-steps),
// 240B-stride rows (no swizzle). Round 14: exact R11 structure (last
// passing) + software-pipelined ldmatrix (fragment double-buffer: k-step
// ks+1's LDSMs issue before ks's HMMAs) + right-sized A buffer.
// 256 CTAs x 128 threads (2x2 warp grid), 2 CTAs/SM.
// ---------------------------------------------------------------------------

#define NCH   64
#define NOUT  64
#define KPAIR 112
#define ROWB  240
#define NPAIR 32

__device__ __align__(16) unsigned short g_Wp[NPAIR * NOUT * KPAIR];
__device__ float g_bias2[NOUT];

// dynamic smem layout (bytes)
#define A_BUF  (64 * ROWB)                   // 15360
#define B_BUF  (NOUT * ROWB)                 // 15360
#define OFF_A  0                             // 2 x A_BUF = 30720
#define OFF_B  (2 * A_BUF)                   // 2 x B_BUF = 30720
#define OFF_X  (OFF_B + 2 * B_BUF)           // 2 x 408 floats = 3264
#define SMEM_SZ (OFF_X + 3264 + 64)

__device__ __forceinline__ uint32_t s2u(const void* p) {
    return (uint32_t)__cvta_generic_to_shared(p);
}
__device__ __forceinline__ void cpa4(uint32_t s, const void* g, bool ok) {
    asm volatile("cp.async.ca.shared.global [%0], [%1], 4, %2;\n"
                 :: "r"(s), "l"(g), "r"(ok ? 4 : 0));
}
__device__ __forceinline__ void cpa16(uint32_t s, const void* g) {
    asm volatile("cp.async.cg.shared.global [%0], [%1], 16;\n"
                 :: "r"(s), "l"(g));
}
__device__ __forceinline__ void ldsm4(uint32_t& r0, uint32_t& r1, uint32_t& r2,
                                      uint32_t& r3, uint32_t addr) {
    asm volatile("ldmatrix.sync.aligned.m8n8.x4.shared.b16 {%0,%1,%2,%3}, [%4];"
                 : "=r"(r0), "=r"(r1), "=r"(r2), "=r"(r3) : "r"(addr));
}
__device__ __forceinline__ void mma16816(float& c0, float& c1, float& c2, float& c3,
                                         uint32_t a0, uint32_t a1, uint32_t a2,
                                         uint32_t a3, uint32_t b0, uint32_t b1) {
    asm volatile(
        "mma.sync.aligned.m16n8k16.row.col.f32.f16.f16.f32 "
        "{%0,%1,%2,%3}, {%4,%5,%6,%7}, {%8,%9}, {%0,%1,%2,%3};"
        : "+f"(c0), "+f"(c1), "+f"(c2), "+f"(c3)
        : "r"(a0), "r"(a1), "r"(a2), "r"(a3), "r"(b0), "r"(b1));
}

// ---------------------------------------------------------------------------
// Prep (exact R11): pack symmetric weights per channel pair.
// ---------------------------------------------------------------------------
__global__ void __launch_bounds__(256)
poly_prep(const float* __restrict__ filters, const float* __restrict__ biases) {
    __shared__ float fsm[NOUT * 100];
    __shared__ __align__(16) unsigned short wsm[NOUT * KPAIR];
    const int pj = blockIdx.x, tid = threadIdx.x;

    #pragma unroll 1
    for (int p = 0; p < 2; ++p) {
        const int c = 2 * pj + p;
        for (int i = tid; i < NOUT * 100; i += 256)
            fsm[i] = filters[(i / 100) * 6400 + c * 100 + (i % 100)];
        __syncthreads();

        if (tid < NOUT) {
            const int o = tid;
            const float* F = fsm + o * 100;
            float v[56];
            int k = 0;
            #pragma unroll
            for (int t = 1; t <= 9; ++t) v[k++] = F[t] + F[t * 10];
            #pragma unroll
            for (int i = 1; i <= 9; ++i)
                #pragma unroll
                for (int j = i; j <= 9; ++j)
                    v[k++] = (i == j) ? F[i * 10 + i]
                                      : (F[i * 10 + j] + F[j * 10 + i]);
            v[54] = 0.0f; v[55] = 0.0f;
            #pragma unroll
            for (int kk = 0; kk < 56; ++kk)
                wsm[o * KPAIR + p * 56 + kk] =
                    __half_as_ushort(__float2half_rn(v[kk]));
        }
        __syncthreads();
    }

    uint4* dst = (uint4*)(g_Wp + pj * NOUT * KPAIR);
    const uint4* srcp = (const uint4*)wsm;
    for (int i = tid; i < 896; i += 256) dst[i] = srcp[i];

    if (pj == 0 && tid < NOUT) {
        float s = biases[tid];
        for (int cc = 0; cc < NCH; ++cc) s += filters[tid * 6400 + cc * 100];
        g_bias2[tid] = s;
    }
}

// ---------------------------------------------------------------------------
// Main kernel: 256 CTAs (b, row) x 128 threads (4 warps), 2x2 warp grid over
// D[64 px, 64 o]; iter = channel pair, K = 112 (7 k-steps), pipelined ldsm.
// ---------------------------------------------------------------------------
extern __shared__ unsigned char smdyn[];

__global__ void __launch_bounds__(128, 2)
poly_mma(const float* __restrict__ x, float* __restrict__ out) {
    const uint32_t smb = s2u(smdyn);
    const int tid = threadIdx.x, lane = tid & 31, wid = tid >> 5;
    const int m = tid & 63, h = tid >> 6;           // pixel col, pair-channel
    const int mrow = wid >> 1, ncol = wid & 1;      // 2x2 warp grid
    const int b = blockIdx.x >> 6;
    const int r = blockIdx.x & 63;

    float acc[2][4][4];
    #pragma unroll
    for (int mt = 0; mt < 2; ++mt)
        #pragma unroll
        for (int n8 = 0; n8 < 4; ++n8)
            #pragma unroll
            for (int q = 0; q < 4; ++q) acc[mt][n8][q] = 0.0f;

    // stage channel pair j into buffer j&1
    auto stage = [&](int j) {
        const uint32_t buf = (uint32_t)(j & 1);
        #pragma unroll
        for (int i = tid; i < 408; i += 128) {      // 2 ch x 3 rows x 68 cols
            const int p = i / 204, rem = i % 204;
            const int rr = rem / 68, col = rem % 68;
            const int gr = r - 1 + rr, gw = col - 1;
            const bool ok = ((unsigned)gr < 64u) && ((unsigned)gw < 64u);
            const int c = 2 * j + p;
            const float* src =
                x + (((b * NCH + c) * 64 + (ok ? gr : 0)) * 64 + (ok ? gw : 0));
            cpa4(smb + OFF_X + (buf * 408 + (uint32_t)i) * 4, src, ok);
        }
        const uint4* srcw = (const uint4*)(g_Wp + j * NOUT * KPAIR);
        #pragma unroll
        for (int i = tid; i < 896; i += 128) {      // 64 rows x 14 x 16B
            const int row = i / 14, col = i % 14;
            cpa16(smb + OFF_B + buf * B_BUF + (uint32_t)(row * ROWB + col * 16),
                  srcw + i);
        }
    };

    stage(0);
    asm volatile("cp.async.commit_group;" ::: "memory");

    // ldmatrix lane base offsets (no swizzle; k-step adds ks*32 bytes)
    uint32_t a_off[2], b_off[2];
    #pragma unroll
    for (int mt = 0; mt < 2; ++mt)
        a_off[mt] = (uint32_t)((mrow * 32 + mt * 16 + (lane & 15)) * ROWB +
                               (lane >> 4) * 16);
    #pragma unroll
    for (int nt = 0; nt < 2; ++nt)
        b_off[nt] = (uint32_t)((ncol * 32 + nt * 16 + (lane & 15)) * ROWB +
                               (lane >> 4) * 16);

    for (int j = 0; j < NPAIR; ++j) {
        asm volatile("cp.async.wait_group 0;" ::: "memory");
        __syncthreads();   // x[j], B[j] ready; A[j&1] free (MMA j-2 done)

        if (j + 1 < NPAIR) stage(j + 1);
        asm volatile("cp.async.commit_group;" ::: "memory");

        const uint32_t abuf = smb + OFF_A + (uint32_t)(j & 1) * A_BUF;
        const uint32_t bbuf = smb + OFF_B + (uint32_t)(j & 1) * B_BUF;

        // ---- featgen: this thread's channel (h) of the pair (exact R11) ----
        {
            const float* xbp =
                (const float*)(smdyn + OFF_X) + (j & 1) * 408 + h * 204;
            float t[9];
            #pragma unroll
            for (int rr = 0; rr < 3; ++rr)
                #pragma unroll
                for (int dx = 0; dx < 3; ++dx)
                    t[rr * 3 + dx] = xbp[rr * 68 + m + dx];

            float fl[54];
            #pragma unroll
            for (int tt = 0; tt < 9; ++tt) fl[tt] = t[tt];
            {
                int k = 9;
                #pragma unroll
                for (int i = 0; i < 9; ++i)
                    #pragma unroll
                    for (int jj = i; jj < 9; ++jj) fl[k++] = t[i] * t[jj];
            }

            uint32_t hr[28];
            #pragma unroll
            for (int u = 0; u < 27; ++u) {
                __half2 hh = __floats2half2_rn(fl[2 * u], fl[2 * u + 1]);
                hr[u] = *reinterpret_cast<uint32_t*>(&hh);
            }
            hr[27] = 0u;   // pad halves 54,55

            const uint32_t dst0 = abuf + (uint32_t)(m * ROWB + h * 112);
            #pragma unroll
            for (int q = 0; q < 7; ++q)
                asm volatile("st.shared.v4.b32 [%0], {%1,%2,%3,%4};"
                             :: "r"(dst0 + (uint32_t)q * 16),
                                "r"(hr[4 * q]), "r"(hr[4 * q + 1]),
                                "r"(hr[4 * q + 2]), "r"(hr[4 * q + 3])
                             : "memory");
        }
        __syncthreads();   // A pair ready

        // ---- HMMA over K = 112: software-pipelined fragments ----
        uint32_t fa0[2][4], fa1[2][4], fbA[2][4], fbB[2][4];
        ldsm4(fa0[0][0], fa0[0][1], fa0[0][2], fa0[0][3], abuf + a_off[0]);
        ldsm4(fa1[0][0], fa1[0][1], fa1[0][2], fa1[0][3], abuf + a_off[1]);
        ldsm4(fbA[0][0], fbA[0][1], fbA[0][2], fbA[0][3], bbuf + b_off[0]);
        ldsm4(fbB[0][0], fbB[0][1], fbB[0][2], fbB[0][3], bbuf + b_off[1]);

        #pragma unroll
        for (int ks = 0; ks < 7; ++ks) {
            const int cur = ks & 1, nxt = cur ^ 1;
            if (ks < 6) {                       // prefetch k-step ks+1
                const uint32_t kl = (uint32_t)(ks + 1) * 32;
                ldsm4(fa0[nxt][0], fa0[nxt][1], fa0[nxt][2], fa0[nxt][3],
                      abuf + a_off[0] + kl);
                ldsm4(fa1[nxt][0], fa1[nxt][1], fa1[nxt][2], fa1[nxt][3],
                      abuf + a_off[1] + kl);
                ldsm4(fbA[nxt][0], fbA[nxt][1], fbA[nxt][2], fbA[nxt][3],
                      bbuf + b_off[0] + kl);
                ldsm4(fbB[nxt][0], fbB[nxt][1], fbB[nxt][2], fbB[nxt][3],
                      bbuf + b_off[1] + kl);
            }
            uint32_t* a0 = fa0[cur];
            uint32_t* a1 = fa1[cur];
            uint32_t* bA = fbA[cur];
            uint32_t* bB = fbB[cur];

            mma16816(acc[0][0][0], acc[0][0][1], acc[0][0][2], acc[0][0][3],
                     a0[0], a0[1], a0[2], a0[3], bA[0], bA[2]);
            mma16816(acc[0][1][0], acc[0][1][1], acc[0][1][2], acc[0][1][3],
                     a0[0], a0[1], a0[2], a0[3], bA[1], bA[3]);
            mma16816(acc[0][2][0], acc[0][2][1], acc[0][2][2], acc[0][2][3],
                     a0[0], a0[1], a0[2], a0[3], bB[0], bB[2]);
            mma16816(acc[0][3][0], acc[0][3][1], acc[0][3][2], acc[0][3][3],
                     a0[0], a0[1], a0[2], a0[3], bB[1], bB[3]);
            mma16816(acc[1][0][0], acc[1][0][1], acc[1][0][2], acc[1][0][3],
                     a1[0], a1[1], a1[2], a1[3], bA[0], bA[2]);
            mma16816(acc[1][1][0], acc[1][1][1], acc[1][1][2], acc[1][1][3],
                     a1[0], a1[1], a1[2], a1[3], bA[1], bA[3]);
            mma16816(acc[1][2][0], acc[1][2][1], acc[1][2][2], acc[1][2][3],
                     a1[0], a1[1], a1[2], a1[3], bB[0], bB[2]);
            mma16816(acc[1][3][0], acc[1][3][1], acc[1][3][2], acc[1][3][3],
                     a1[0], a1[1], a1[2], a1[3], bB[1], bB[3]);
        }
    }

    // ---- epilogue: c-frag -> global, + bias ----
    const int obase = ncol * 32 + (lane & 3) * 2;
    float2 bias2v[4];
    #pragma unroll
    for (int n8 = 0; n8 < 4; ++n8)
        bias2v[n8] = *(const float2*)(g_bias2 + obase + n8 * 8);

    #pragma unroll
    for (int mt = 0; mt < 2; ++mt) {
        #pragma unroll
        for (int half = 0; half < 2; ++half) {
            const int cc = mrow * 32 + mt * 16 + (lane >> 2) + half * 8;
            float* op = out + ((b * NOUT) * 64 + r) * 64 + cc;
            #pragma unroll
            for (int n8 = 0; n8 < 4; ++n8) {
                const int o = obase + n8 * 8;
                op[(o)     * 4096] = acc[mt][n8][half * 2]     + bias2v[n8].x;
                op[(o + 1) * 4096] = acc[mt][n8][half * 2 + 1] + bias2v[n8].y;
            }
        }
    }
}

// ---------------------------------------------------------------------------
extern "C" void kernel_launch(void* const* d_in, const int* in_sizes, int n_in,
                              void* d_out, int out_size) {
    const float* x       = (const float*)d_in[0];  // [4,64,64,64]
    const float* filters = (const float*)d_in[1];  // [64,64,10,10]
    const float* biases  = (const float*)d_in[2];  // [64,1]
    float* out = (float*)d_out;                    // [4,64,64,64]
    (void)in_sizes; (void)n_in; (void)out_size;

    static int attr_set = 0;
    if (!attr_set) {
        cudaFuncSetAttribute(poly_mma,
                             cudaFuncAttributeMaxDynamicSharedMemorySize,
                             SMEM_SZ);
        attr_set = 1;
    }
    poly_prep<<<32, 256>>>(filters, biases);
    poly_mma<<<256, 128, SMEM_SZ>>>(x, out);
}